// round 3
// baseline (speedup 1.0000x reference)
#include <cuda_runtime.h>

typedef unsigned long long ull;

#define TT 1024
#define BB 32
#define DD 768
#define LLn 48

// Scratch (static device globals — no allocation)
__device__ float g_em[TT * BB * LLn];   // emissions [T,B,L]
__device__ float g_res[64];             // [0..31]=fwd logZ, [32..63]=partial logZ
__device__ int   g_bool_dt;             // 0=uint8, 1=int32, 2=float32

__device__ __forceinline__ ull pack2(float x, float y) {
    ull r; asm("mov.b64 %0, {%1,%2};" : "=l"(r) : "f"(x), "f"(y)); return r;
}
__device__ __forceinline__ void unpack2(ull v, float& x, float& y) {
    asm("mov.b64 {%0,%1}, %2;" : "=f"(x), "=f"(y) : "l"(v));
}
__device__ __forceinline__ ull fma2(ull a, ull b, ull c) {
    ull d; asm("fma.rn.f32x2 %0, %1, %2, %3;" : "=l"(d) : "l"(a), "l"(b), "l"(c)); return d;
}
__device__ __forceinline__ ull add2(ull a, ull b) {
    ull d; asm("add.rn.f32x2 %0, %1, %2;" : "=l"(d) : "l"(a), "l"(b)); return d;
}

__device__ __forceinline__ int loadBool(const void* p, int dt, long idx) {
    if (dt == 1) return ((const int*)p)[idx] != 0;
    if (dt == 0) return ((const unsigned char*)p)[idx] != 0;
    return ((const float*)p)[idx] != 0.f;
}

// ---------------------------------------------------------------------------
// Detect boolean storage dtype from the tags buffer (T*B*L elements, ~30% true).
//   float32: some word == 0x3F800000 (1.0f)
//   uint8  : packed bytes -> some word has nonzero bits above byte 0
//   int32  : otherwise (all words 0 or 1)
// ---------------------------------------------------------------------------
__global__ void detect_kernel(const unsigned int* __restrict__ w) {
    int seen_f32 = 0, seen_u8 = 0;
    for (int i = 0; i < 1024; i++) {
        unsigned int v = w[i];
        if (v == 0x3F800000u) seen_f32 = 1;
        else if (v & 0xFFFFFF00u) seen_u8 = 1;
    }
    g_bool_dt = seen_f32 ? 2 : (seen_u8 ? 0 : 1);
}

// ---------------------------------------------------------------------------
// Emissions GEMM: em[t,b,j] = feats[t,b,:] . W[:,j] + bias[j]
// 32768 rows x 768 x 48, one row per thread, packed f32x2 FMA (2 MAC/instr).
// ---------------------------------------------------------------------------
__global__ __launch_bounds__(256) void emis_kernel(const float* __restrict__ feats,
                                                   const float* __restrict__ W,
                                                   const float* __restrict__ bias) {
    __shared__ float Ws[64 * LLn];  // one K-tile of W: 64 x 48 floats = 12 KB
    const int tid = threadIdx.x;
    const int row = blockIdx.x * 256 + tid;  // 0..32767 == t*32 + b
    const float4* frow = (const float4*)(feats + (size_t)row * DD);

    ull acc[24];
#pragma unroll
    for (int i = 0; i < 24; i++) acc[i] = 0ull;

    for (int kt = 0; kt < 12; ++kt) {
        __syncthreads();  // protect previous tile reads
        const float4* wg = (const float4*)(W + kt * 64 * LLn);
        float4* ws4 = (float4*)Ws;
#pragma unroll
        for (int i = 0; i < 3; i++) ws4[tid + 256 * i] = wg[tid + 256 * i];
        __syncthreads();
#pragma unroll
        for (int half = 0; half < 2; ++half) {
            float4 fv[8];
#pragma unroll
            for (int i = 0; i < 8; i++) fv[i] = frow[kt * 16 + half * 8 + i];
#pragma unroll
            for (int i = 0; i < 8; i++) {
                float fx0 = fv[i].x, fx1 = fv[i].y, fx2 = fv[i].z, fx3 = fv[i].w;
#pragma unroll
                for (int cc = 0; cc < 4; ++cc) {
                    float f = (cc == 0) ? fx0 : (cc == 1) ? fx1 : (cc == 2) ? fx2 : fx3;
                    ull fd = pack2(f, f);
                    const ull* wrow = (const ull*)(Ws + (half * 32 + i * 4 + cc) * LLn);
#pragma unroll
                    for (int jp = 0; jp < 24; jp++) acc[jp] = fma2(fd, wrow[jp], acc[jp]);
                }
            }
        }
    }
    float* orow = g_em + (size_t)row * LLn;
#pragma unroll
    for (int jp = 0; jp < 24; jp++) {
        float x, y; unpack2(acc[jp], x, y);
        float2 o; o.x = x + bias[2 * jp]; o.y = y + bias[2 * jp + 1];
        ((float2*)orow)[jp] = o;
    }
}

// ---------------------------------------------------------------------------
// CRF forward scan in linear domain with carried log-offset c.
// One CTA per (scan, batch): blockIdx 0..31 = unconstrained, 32..63 = partial.
// Threads 0..47 each own label j: exp(trans[j,:]) held in 24 packed regs.
// ---------------------------------------------------------------------------
__global__ __launch_bounds__(64) void scan_kernel(const void* __restrict__ tags,
                                                  const int* __restrict__ lens,
                                                  const float* __restrict__ beg,
                                                  const float* __restrict__ trans,
                                                  const float* __restrict__ endv,
                                                  const void* __restrict__ bc,
                                                  const void* __restrict__ ec,
                                                  const void* __restrict__ tc) {
    __shared__ float ubuf[2][LLn];
    __shared__ float scratch[LLn];
    const int tid = threadIdx.x;
    const int bidx = blockIdx.x;
    const bool is_par = bidx >= BB;
    const int b = bidx & (BB - 1);
    const int j = tid;
    const bool active = tid < LLn;
    const int len = lens[b];
    const int lenm1 = len - 1;
    const int dt = g_bool_dt;

    ull E2[24];
    float Eend = 0.f;
    if (active) {
#pragma unroll
        for (int kp = 0; kp < 24; kp++) {
            float a0 = trans[j * LLn + 2 * kp];
            float a1 = trans[j * LLn + 2 * kp + 1];
            float e0 = __expf(a0), e1 = __expf(a1);
            if (is_par) {
                if (loadBool(tc, dt, j * LLn + 2 * kp))     e0 = 0.f;
                if (loadBool(tc, dt, j * LLn + 2 * kp + 1)) e1 = 0.f;
            }
            E2[kp] = pack2(e0, e1);
        }
        float ev = __expf(endv[j]);
        if (is_par && loadBool(ec, dt, j)) ev = 0.f;
        Eend = ev;
        // t = 0 init
        float x = g_em[b * LLn + j] + beg[j];
        float u0 = __expf(x);
        if (is_par) {
            if (loadBool(bc, dt, j) || loadBool(tags, dt, b * LLn + j)) u0 = 0.f;
        }
        ubuf[0][j] = u0;
    }

    float c = 0.f;
    int rcnt = 6;
    int p = 0;
    int t = 1;
    bool fin = (lenm1 <= 0);

    auto emload = [&](int tt) -> float {
        int tq = (tt <= TT - 1) ? tt : (TT - 1);
        return active ? __ldg(&g_em[(tq * BB + b) * LLn + j]) : 0.f;
    };
    auto tgload = [&](int tt) -> int {
        int tq = (tt <= TT - 1) ? tt : (TT - 1);
        return (is_par && active) ? loadBool(tags, dt, (long)(tq * BB + b) * LLn + j) : 0;
    };

    auto do_step = [&](float PE, int PT) {
        __syncthreads();  // u[p] from previous step is visible
        float unew = 0.f;
        if (active) {
            float Eem = __expf(PE);
            bool ren = (--rcnt == 0);
            const ulonglong2* uu = (const ulonglong2*)(ubuf[p]);
            ull a0 = 0, a1 = 0, a2 = 0, a3 = 0;
#pragma unroll
            for (int i = 0; i < 6; i++) {
                ulonglong2 q0 = uu[2 * i];
                ulonglong2 q1 = uu[2 * i + 1];
                a0 = fma2(E2[4 * i],     q0.x, a0);
                a1 = fma2(E2[4 * i + 1], q0.y, a1);
                a2 = fma2(E2[4 * i + 2], q1.x, a2);
                a3 = fma2(E2[4 * i + 3], q1.y, a3);
            }
            a0 = add2(a0, a2); a1 = add2(a1, a3); a0 = add2(a0, a1);
            float lo, hi; unpack2(a0, lo, hi);
            float s = lo + hi;
            float scale = 1.f;
            if (ren) {
                rcnt = 6;
                const float4* u4 = (const float4*)(ubuf[p]);
                float4 m4 = u4[0];
#pragma unroll
                for (int i = 1; i < 12; i++) {
                    float4 q = u4[i];
                    m4.x = fmaxf(m4.x, q.x); m4.y = fmaxf(m4.y, q.y);
                    m4.z = fmaxf(m4.z, q.z); m4.w = fmaxf(m4.w, q.w);
                }
                float m = fmaxf(fmaxf(m4.x, m4.y), fmaxf(m4.z, m4.w));
                m = fmaxf(m, 1e-35f);
                scale = __fdividef(1.f, m);
                c += logf(m);
            }
            float val = s * scale * Eem;
            if (is_par && PT) val = 0.f;
            ubuf[p ^ 1][j] = val;
            unew = val;
        }
        if (t == lenm1) {  // uniform across CTA
            if (active) scratch[j] = unew * Eend;
            __syncthreads();
            if (tid == 0) {
                const float4* s4 = (const float4*)scratch;
                float acc0 = 0.f;
#pragma unroll
                for (int i = 0; i < 12; i++) {
                    float4 q = s4[i];
                    acc0 += (q.x + q.y) + (q.z + q.w);
                }
                g_res[bidx] = c + logf(acc0);
            }
            fin = true;
        }
        p ^= 1;
    };

    // depth-4 register prefetch pipeline for em/tags
    float peA = emload(1), peB = emload(2), peC = emload(3), peD = emload(4);
    int ptA = tgload(1), ptB = tgload(2), ptC = tgload(3), ptD = tgload(4);

    while (!fin) {
        do_step(peA, ptA); if (fin) break; peA = emload(t + 4); ptA = tgload(t + 4); ++t;
        do_step(peB, ptB); if (fin) break; peB = emload(t + 4); ptB = tgload(t + 4); ++t;
        do_step(peC, ptC); if (fin) break; peC = emload(t + 4); ptC = tgload(t + 4); ++t;
        do_step(peD, ptD); if (fin) break; peD = emload(t + 4); ptD = tgload(t + 4); ++t;
    }
}

__global__ void combine_kernel(float* __restrict__ out) {
    int i = threadIdx.x;
    if (i < BB) out[i] = g_res[i] - g_res[BB + i];
}

extern "C" void kernel_launch(void* const* d_in, const int* in_sizes, int n_in,
                              void* d_out, int out_size) {
    const float* feats = (const float*)d_in[0];
    const void*  tags  = d_in[1];
    const int*   lens  = (const int*)d_in[2];
    const float* W     = (const float*)d_in[3];
    const float* bias  = (const float*)d_in[4];
    const float* beg   = (const float*)d_in[5];
    const float* trans = (const float*)d_in[6];
    const float* endv  = (const float*)d_in[7];
    const void*  bc    = d_in[8];
    const void*  ec    = d_in[9];
    const void*  tc    = d_in[10];

    detect_kernel<<<1, 1>>>((const unsigned int*)tags);
    emis_kernel<<<128, 256>>>(feats, W, bias);
    scan_kernel<<<64, 64>>>(tags, lens, beg, trans, endv, bc, ec, tc);
    combine_kernel<<<1, 32>>>((float*)d_out);
}